// round 10
// baseline (speedup 1.0000x reference)
#include <cuda_runtime.h>
#include <cstdint>

#define BATCH 4
#define SEQ   2048
#define INF   4096
#define OUTF  4096
#define RANK  16
// SCALING = 16/16 = 1.0f (elided)

// ---- phase-1 (warp MMA) ----
#define P1_T      256
#define P1_ROWS   128                 // rows per CTA (8 warps x m16)
#define P1_SPLIT  8
#define KS_TOT    (INF / 16)          // 256 k-steps
#define KS_SPLIT  (KS_TOT / P1_SPLIT) // 32

#define NRT       (BATCH * SEQ / 16)  // 512 row-tiles
#define NOT       (OUTF / 8)          // 512 o-tiles

typedef unsigned long long ull;

// scratch
__device__ float    g_bx[P1_SPLIT * BATCH * SEQ * RANK];   // 4 MB fp32 partials
__device__ uint32_t g_Bc[8 * 2 * KS_TOT * 2 * 2 * 32];     // 2 MB packed B
__device__ uint32_t g_Af[8 * NOT * 128];                   // 2 MB packed A
__device__ uint32_t g_bxf[NRT * 256];                      // 512 KB packed Bx frags

// ---- helpers --------------------------------------------------------------
__device__ __forceinline__ uint32_t bfhi2(float f0, float f1) {
    return __byte_perm(__float_as_uint(f0), __float_as_uint(f1), 0x7632);
}
__device__ __forceinline__ uint32_t bflo2(float f0, float f1) {
    const float l0 = f0 - __uint_as_float(__float_as_uint(f0) & 0xFFFF0000u);
    const float l1 = f1 - __uint_as_float(__float_as_uint(f1) & 0xFFFF0000u);
    return __byte_perm(__float_as_uint(l0), __float_as_uint(l1), 0x7632);
}
__device__ __forceinline__ void mma16816(float* d,
    uint32_t a0, uint32_t a1, uint32_t a2, uint32_t a3,
    uint32_t b0, uint32_t b1)
{
    asm volatile(
        "mma.sync.aligned.m16n8k16.row.col.f32.bf16.bf16.f32 "
        "{%0,%1,%2,%3}, {%4,%5,%6,%7}, {%8,%9}, {%0,%1,%2,%3};"
        : "+f"(d[0]), "+f"(d[1]), "+f"(d[2]), "+f"(d[3])
        : "r"(a0), "r"(a1), "r"(a2), "r"(a3), "r"(b0), "r"(b1));
}

// ---------------------------------------------------------------------------
// K0a: pack B[8][16][4096] -> b-frag bf16 hi/lo.
// word idx = ((((a*2+h)*KS_TOT + ks)*2 + j)*2 + t)*32 + lane
//   element: rank = t*8 + lane>>2, k = ks*16 + j*8 + (lane&3)*2 (+pair)
// 8 words per thread.
// ---------------------------------------------------------------------------
__global__ void lora_conv_b(const float* __restrict__ Bw)
{
    const int idx  = blockIdx.x * blockDim.x + threadIdx.x;   // 8*256*32
    const int lane = idx & 31;
    const int ks   = (idx >> 5) & (KS_TOT - 1);
    const int a    = idx >> 13;
#pragma unroll
    for (int t = 0; t < 2; ++t) {
        const int r = t * 8 + (lane >> 2);
        const float* p = Bw + ((size_t)a * RANK + r) * INF + ks * 16 + (lane & 3) * 2;
#pragma unroll
        for (int j = 0; j < 2; ++j) {
            const float f0 = p[j * 8], f1 = p[j * 8 + 1];
            const uint32_t off = (uint32_t)(((ks * 2 + j) * 2 + t) * 32 + lane);
            g_Bc[(uint32_t)(a * 2 + 0) * (KS_TOT * 128) + off] = bfhi2(f0, f1);
            g_Bc[(uint32_t)(a * 2 + 1) * (KS_TOT * 128) + off] = bflo2(f0, f1);
        }
    }
}

// ---------------------------------------------------------------------------
// K0b: pack A[8][4096][16] -> b-frag bf16 hi/lo for phase 2.
// word idx = (a*NOT + ot)*128 + h*64 + j*32 + lane
//   element: o = ot*8 + lane>>2, r = j*8 + (lane&3)*2 (+pair)
// ---------------------------------------------------------------------------
__global__ void lora_conv_a(const float* __restrict__ Aw)
{
    const int idx  = blockIdx.x * blockDim.x + threadIdx.x;   // 8*512*32
    const int lane = idx & 31;
    const int ot   = (idx >> 5) & (NOT - 1);
    const int a    = idx >> 14;
    const int o    = ot * 8 + (lane >> 2);
    const float* p = Aw + ((size_t)a * OUTF + o) * RANK + (lane & 3) * 2;
    uint32_t* dst  = g_Af + (uint32_t)(a * NOT + ot) * 128u + lane;
#pragma unroll
    for (int j = 0; j < 2; ++j) {
        const float f0 = p[j * 8], f1 = p[j * 8 + 1];
        dst[j * 32]      = bfhi2(f0, f1);
        dst[64 + j * 32] = bflo2(f0, f1);
    }
}

// ---------------------------------------------------------------------------
// K1: phase-1 tensor MMA (split-bf16, 3 terms). Warp = m16 row tile.
// K split 8 ways -> 512 CTAs. No smem, no barriers.
// ---------------------------------------------------------------------------
__global__ __launch_bounds__(P1_T) void lora_p1_mma(
    const float* __restrict__ x,
    const int*   __restrict__ ids)
{
    const int tid  = threadIdx.x;
    const int wid  = tid >> 5;
    const int lane = tid & 31;
    const int tig  = lane & 3;
    const int b    = blockIdx.y;
    const int sp   = blockIdx.z;
    const int aid  = ids[b];

    const int row0 = blockIdx.x * P1_ROWS + wid * 16 + (lane >> 2);
    const float* xr0 = x + ((size_t)b * SEQ + row0) * INF;
    const float* xr8 = xr0 + 8 * INF;

    const uint32_t* Bhi = g_Bc + (size_t)(aid * 2 + 0) * (KS_TOT * 128);
    const uint32_t* Blo = g_Bc + (size_t)(aid * 2 + 1) * (KS_TOT * 128);

    float acc0[4] = {0.f, 0.f, 0.f, 0.f};   // ranks 0-7
    float acc1[4] = {0.f, 0.f, 0.f, 0.f};   // ranks 8-15

    const int ks0 = sp * KS_SPLIT;
#pragma unroll 4
    for (int ks = ks0; ks < ks0 + KS_SPLIT; ++ks) {
        const int k = ks * 16 + tig * 2;
        const float2 f0 = *(const float2*)(xr0 + k);
        const float2 f1 = *(const float2*)(xr8 + k);
        const float2 f2 = *(const float2*)(xr0 + k + 8);
        const float2 f3 = *(const float2*)(xr8 + k + 8);

        const uint32_t ah0 = bfhi2(f0.x, f0.y), ah1 = bfhi2(f1.x, f1.y);
        const uint32_t ah2 = bfhi2(f2.x, f2.y), ah3 = bfhi2(f3.x, f3.y);
        const uint32_t al0 = bflo2(f0.x, f0.y), al1 = bflo2(f1.x, f1.y);
        const uint32_t al2 = bflo2(f2.x, f2.y), al3 = bflo2(f3.x, f3.y);

        const uint32_t* bp = Bhi + ks * 128 + lane;
        const uint32_t* lp = Blo + ks * 128 + lane;
        const uint32_t bh00 = bp[0],  bh01 = bp[64];   // t=0 (ranks 0-7)
        const uint32_t bh10 = bp[32], bh11 = bp[96];   // t=1 (ranks 8-15)
        const uint32_t bl00 = lp[0],  bl01 = lp[64];
        const uint32_t bl10 = lp[32], bl11 = lp[96];

        mma16816(acc0, ah0, ah1, ah2, ah3, bh00, bh01);
        mma16816(acc0, al0, al1, al2, al3, bh00, bh01);
        mma16816(acc0, ah0, ah1, ah2, ah3, bl00, bl01);
        mma16816(acc1, ah0, ah1, ah2, ah3, bh10, bh11);
        mma16816(acc1, al0, al1, al2, al3, bh10, bh11);
        mma16816(acc1, ah0, ah1, ah2, ah3, bl10, bl11);
    }

    float* d0 = g_bx + ((size_t)(sp * BATCH + b) * SEQ + row0) * RANK;
    float* d8 = d0 + 8 * RANK;
    *(float2*)(d0 + tig * 2)     = make_float2(acc0[0], acc0[1]);
    *(float2*)(d8 + tig * 2)     = make_float2(acc0[2], acc0[3]);
    *(float2*)(d0 + 8 + tig * 2) = make_float2(acc1[0], acc1[1]);
    *(float2*)(d8 + 8 + tig * 2) = make_float2(acc1[2], acc1[3]);
}

// ---------------------------------------------------------------------------
// K1b: reduce 8 Bx partials -> packed a-frag hi/lo per row-tile.
// g_bxf word idx = rt*256 + h*128 + q*32 + lane;  frag order q = a0,a1,a2,a3:
//   a0=(row,k0) a1=(row+8,k0) a2=(row,k0+8) a3=(row+8,k0+8),
//   row = rt*16 + lane>>2, k0 = (lane&3)*2.
// ---------------------------------------------------------------------------
__global__ __launch_bounds__(256) void lora_p1_reduce()
{
    const int tid  = threadIdx.x;
    const int wid  = tid >> 5;
    const int lane = tid & 31;
    const int rt   = blockIdx.x * 8 + wid;        // 0..511
    const int row  = rt * 16 + (lane >> 2);       // global row
    const int k0   = (lane & 3) * 2;

    float2 s00 = {0.f, 0.f}, s01 = {0.f, 0.f};
    float2 s10 = {0.f, 0.f}, s11 = {0.f, 0.f};
#pragma unroll
    for (int sp = 0; sp < P1_SPLIT; ++sp) {
        const float* p = g_bx + ((size_t)sp * (BATCH * SEQ) + row) * RANK;
        const float* q = p + 8 * RANK;
        const float2 v00 = *(const float2*)(p + k0);
        const float2 v01 = *(const float2*)(p + k0 + 8);
        const float2 v10 = *(const float2*)(q + k0);
        const float2 v11 = *(const float2*)(q + k0 + 8);
        s00.x += v00.x; s00.y += v00.y;  s01.x += v01.x; s01.y += v01.y;
        s10.x += v10.x; s10.y += v10.y;  s11.x += v11.x; s11.y += v11.y;
    }
    uint32_t* dst = g_bxf + (uint32_t)rt * 256u + lane;
    dst[0]   = bfhi2(s00.x, s00.y);   // a0 hi
    dst[32]  = bfhi2(s10.x, s10.y);   // a1 hi
    dst[64]  = bfhi2(s01.x, s01.y);   // a2 hi
    dst[96]  = bfhi2(s11.x, s11.y);   // a3 hi
    dst[128] = bflo2(s00.x, s00.y);   // a0 lo
    dst[160] = bflo2(s10.x, s10.y);
    dst[192] = bflo2(s01.x, s01.y);
    dst[224] = bflo2(s11.x, s11.y);
}

// ---------------------------------------------------------------------------
// K2: phase-2 tensor MMA. Warp = one row-tile x 64 o-tiles.
// Per o-tile: 4 LDG.32 (A frags) + 3 MMA + 4 STG.64 -> 128 outputs.
// ---------------------------------------------------------------------------
__global__ __launch_bounds__(256) void lora_p2_mma(
    const int* __restrict__ ids,
    float*     __restrict__ out)
{
    const int tid  = threadIdx.x;
    const int wid  = tid >> 5;
    const int lane = tid & 31;
    const int oc   = blockIdx.x;                  // o-chunk 0..7
    const int rt   = blockIdx.y * 8 + wid;        // row-tile 0..511
    const int b    = rt >> 7;
    const int nt   = rt & 127;
    const int aid  = ids[b];

    // load Bx a-frags (hi + lo)
    const uint32_t* f = g_bxf + (uint32_t)rt * 256u + lane;
    const uint32_t ah0 = f[0],   ah1 = f[32],  ah2 = f[64],  ah3 = f[96];
    const uint32_t al0 = f[128], al1 = f[160], al2 = f[192], al3 = f[224];

    const uint32_t* Ab = g_Af + (size_t)aid * (NOT * 128);
    float* outb = out + ((size_t)b * SEQ + nt * 16) * OUTF;
    const int r  = lane >> 2;
    const int co = (lane & 3) * 2;

#pragma unroll 4
    for (int ot = oc * 64; ot < oc * 64 + 64; ++ot) {
        const uint32_t* ap = Ab + ot * 128 + lane;
        const uint32_t bh0 = ap[0],  bh1 = ap[32];
        const uint32_t bl0 = ap[64], bl1 = ap[96];
        float c[4] = {0.f, 0.f, 0.f, 0.f};
        mma16816(c, ah0, ah1, ah2, ah3, bh0, bh1);   // hi*hi
        mma16816(c, al0, al1, al2, al3, bh0, bh1);   // lo*hi
        mma16816(c, ah0, ah1, ah2, ah3, bl0, bl1);   // hi*lo
        float* d = outb + (size_t)r * OUTF + ot * 8 + co;
        *(float2*)(d)            = make_float2(c[0], c[1]);
        *(float2*)(d + 8 * OUTF) = make_float2(c[2], c[3]);
    }
}

// ---------------------------------------------------------------------------
extern "C" void kernel_launch(void* const* d_in, const int* in_sizes, int n_in,
                              void* d_out, int out_size)
{
    const float* x   = (const float*)d_in[0];   // [4,2048,4096]
    const float* Aw  = (const float*)d_in[1];   // [8,4096,16]
    const float* Bw  = (const float*)d_in[2];   // [8,16,4096]
    const int*   ids = (const int*)  d_in[3];   // [4]
    float*       out = (float*)d_out;           // [4,2048,4096]

    lora_conv_b<<<(8 * KS_TOT * 32) / 256, 256>>>(Bw);    // 256 CTAs
    lora_conv_a<<<(8 * NOT * 32) / 256, 256>>>(Aw);       // 512 CTAs

    dim3 g1(SEQ / P1_ROWS, BATCH, P1_SPLIT);              // (16,4,8) = 512 CTAs
    lora_p1_mma<<<g1, P1_T>>>(x, ids);

    lora_p1_reduce<<<NRT / 8, 256>>>();                   // 64 CTAs

    dim3 g2(OUTF / 512, NRT / 8);                         // (8,64) = 512 CTAs
    lora_p2_mma<<<g2, 256>>>(ids, out);
}

// round 11
// speedup vs baseline: 1.1503x; 1.1503x over previous
#include <cuda_runtime.h>
#include <cstdint>

#define BATCH 4
#define SEQ   2048
#define INF   4096
#define OUTF  4096
#define RANK  16
// SCALING = 16/16 = 1.0f (elided)

// ---- phase-1 (warp MMA) ----
#define P1_T      256
#define P1_ROWS   128                 // rows per CTA (8 warps x m16)
#define P1_SPLIT  8
#define KS_TOT    (INF / 16)          // 256 k-steps
#define KS_SPLIT  (KS_TOT / P1_SPLIT) // 32

// ---- phase-2 (SIMT, proven R7) ----
#define T2     256
#define ROWS2  128
#define OPT    4
#define OTILE  (T2 * OPT)             // 1024
#define BXP    9

typedef unsigned long long ull;

// scratch
__device__ float    g_bx[P1_SPLIT * BATCH * SEQ * RANK];   // 4 MB fp32 partials
__device__ uint32_t g_Bc[8 * 2 * KS_TOT * 2 * 2 * 32];     // 2 MB packed B

// ---- helpers --------------------------------------------------------------
__device__ __forceinline__ void fma2(ull& d, ull a, ull b) {
    asm("fma.rn.f32x2 %0, %1, %2, %0;" : "+l"(d) : "l"(a), "l"(b));
}
__device__ __forceinline__ ull pack2(float lo, float hi) {
    ull d; asm("mov.b64 %0, {%1, %2};" : "=l"(d) : "f"(lo), "f"(hi)); return d;
}
__device__ __forceinline__ void unpack2(float& lo, float& hi, ull d) {
    asm("mov.b64 {%0, %1}, %2;" : "=f"(lo), "=f"(hi) : "l"(d));
}
__device__ __forceinline__ uint32_t bfhi2(float f0, float f1) {
    return __byte_perm(__float_as_uint(f0), __float_as_uint(f1), 0x7632);
}
__device__ __forceinline__ uint32_t bflo2(float f0, float f1) {
    const float l0 = f0 - __uint_as_float(__float_as_uint(f0) & 0xFFFF0000u);
    const float l1 = f1 - __uint_as_float(__float_as_uint(f1) & 0xFFFF0000u);
    return __byte_perm(__float_as_uint(l0), __float_as_uint(l1), 0x7632);
}
__device__ __forceinline__ void mma16816(float* d,
    uint32_t a0, uint32_t a1, uint32_t a2, uint32_t a3,
    uint32_t b0, uint32_t b1)
{
    asm volatile(
        "mma.sync.aligned.m16n8k16.row.col.f32.bf16.bf16.f32 "
        "{%0,%1,%2,%3}, {%4,%5,%6,%7}, {%8,%9}, {%0,%1,%2,%3};"
        : "+f"(d[0]), "+f"(d[1]), "+f"(d[2]), "+f"(d[3])
        : "r"(a0), "r"(a1), "r"(a2), "r"(a3), "r"(b0), "r"(b1));
}

// ---------------------------------------------------------------------------
// K0: pack B[8][16][4096] -> b-frag bf16 hi/lo.
// word idx = ((((a*2+h)*KS_TOT + ks)*2 + j)*2 + t)*32 + lane
//   element: rank = t*8 + lane>>2, k = ks*16 + j*8 + (lane&3)*2 (+pair)
// ---------------------------------------------------------------------------
__global__ void lora_conv_b(const float* __restrict__ Bw)
{
    const int idx  = blockIdx.x * blockDim.x + threadIdx.x;   // 8*256*32
    const int lane = idx & 31;
    const int ks   = (idx >> 5) & (KS_TOT - 1);
    const int a    = idx >> 13;
#pragma unroll
    for (int t = 0; t < 2; ++t) {
        const int r = t * 8 + (lane >> 2);
        const float* p = Bw + ((size_t)a * RANK + r) * INF + ks * 16 + (lane & 3) * 2;
#pragma unroll
        for (int j = 0; j < 2; ++j) {
            const float f0 = p[j * 8], f1 = p[j * 8 + 1];
            const uint32_t off = (uint32_t)(((ks * 2 + j) * 2 + t) * 32 + lane);
            g_Bc[(uint32_t)(a * 2 + 0) * (KS_TOT * 128) + off] = bfhi2(f0, f1);
            g_Bc[(uint32_t)(a * 2 + 1) * (KS_TOT * 128) + off] = bflo2(f0, f1);
        }
    }
}

// ---------------------------------------------------------------------------
// K1: phase-1 tensor MMA (split-bf16, 3 terms). Warp = m16 row tile.
// K split 8 ways -> 512 CTAs. No smem, no barriers.
// ---------------------------------------------------------------------------
__global__ __launch_bounds__(P1_T) void lora_p1_mma(
    const float* __restrict__ x,
    const int*   __restrict__ ids)
{
    const int tid  = threadIdx.x;
    const int wid  = tid >> 5;
    const int lane = tid & 31;
    const int tig  = lane & 3;
    const int b    = blockIdx.y;
    const int sp   = blockIdx.z;
    const int aid  = ids[b];

    const int row0 = blockIdx.x * P1_ROWS + wid * 16 + (lane >> 2);
    const float* xr0 = x + ((size_t)b * SEQ + row0) * INF;
    const float* xr8 = xr0 + 8 * INF;

    const uint32_t* Bhi = g_Bc + (size_t)(aid * 2 + 0) * (KS_TOT * 128);
    const uint32_t* Blo = g_Bc + (size_t)(aid * 2 + 1) * (KS_TOT * 128);

    float acc0[4] = {0.f, 0.f, 0.f, 0.f};   // ranks 0-7
    float acc1[4] = {0.f, 0.f, 0.f, 0.f};   // ranks 8-15

    const int ks0 = sp * KS_SPLIT;
#pragma unroll 4
    for (int ks = ks0; ks < ks0 + KS_SPLIT; ++ks) {
        const int k = ks * 16 + tig * 2;
        const float2 f0 = *(const float2*)(xr0 + k);
        const float2 f1 = *(const float2*)(xr8 + k);
        const float2 f2 = *(const float2*)(xr0 + k + 8);
        const float2 f3 = *(const float2*)(xr8 + k + 8);

        const uint32_t ah0 = bfhi2(f0.x, f0.y), ah1 = bfhi2(f1.x, f1.y);
        const uint32_t ah2 = bfhi2(f2.x, f2.y), ah3 = bfhi2(f3.x, f3.y);
        const uint32_t al0 = bflo2(f0.x, f0.y), al1 = bflo2(f1.x, f1.y);
        const uint32_t al2 = bflo2(f2.x, f2.y), al3 = bflo2(f3.x, f3.y);

        const uint32_t* bp = Bhi + ks * 128 + lane;
        const uint32_t* lp = Blo + ks * 128 + lane;
        const uint32_t bh00 = bp[0],  bh01 = bp[64];   // ranks 0-7
        const uint32_t bh10 = bp[32], bh11 = bp[96];   // ranks 8-15
        const uint32_t bl00 = lp[0],  bl01 = lp[64];
        const uint32_t bl10 = lp[32], bl11 = lp[96];

        mma16816(acc0, ah0, ah1, ah2, ah3, bh00, bh01);
        mma16816(acc0, al0, al1, al2, al3, bh00, bh01);
        mma16816(acc0, ah0, ah1, ah2, ah3, bl00, bl01);
        mma16816(acc1, ah0, ah1, ah2, ah3, bh10, bh11);
        mma16816(acc1, al0, al1, al2, al3, bh10, bh11);
        mma16816(acc1, ah0, ah1, ah2, ah3, bl10, bl11);
    }

    float* d0 = g_bx + ((size_t)(sp * BATCH + b) * SEQ + row0) * RANK;
    float* d8 = d0 + 8 * RANK;
    *(float2*)(d0 + tig * 2)     = make_float2(acc0[0], acc0[1]);
    *(float2*)(d8 + tig * 2)     = make_float2(acc0[2], acc0[3]);
    *(float2*)(d0 + 8 + tig * 2) = make_float2(acc1[0], acc1[1]);
    *(float2*)(d8 + 8 + tig * 2) = make_float2(acc1[2], acc1[3]);
}

// ---------------------------------------------------------------------------
// Phase 2 (fused split-reduce): out[b][n][o] = sum_r Bx[b][n][r]*A[aid][o][r]
// Thread owns 4 consecutive o; A pairs (32 ull) in regs; Bx dup'd in smem.
// 2 rows/iter -> 8 independent fma2 chains. 2 CTAs/SM.  [R7, measured ~34us]
// ---------------------------------------------------------------------------
__global__ __launch_bounds__(T2, 2) void lora_phase2(
    const float* __restrict__ Aw,
    const int*   __restrict__ ids,
    float*       __restrict__ out)
{
    __shared__ ulonglong2 bxd[ROWS2 * BXP];      // 18.4 KB

    const int tid = threadIdx.x;
    const int o   = blockIdx.x * OTILE + tid * OPT;
    const int n0  = blockIdx.y * ROWS2;
    const int b   = blockIdx.z;
    const int aid = ids[b];

    // A pairs: ap01[r] = (A[o][r], A[o+1][r]); ap23[r] = (A[o+2][r], A[o+3][r])
    ull ap01[16], ap23[16];
    {
        const float* Ab = Aw + ((size_t)aid * OUTF + o) * RANK;
        float a0[16], a1[16], a2[16], a3[16];
#pragma unroll
        for (int j = 0; j < 4; ++j) {
            float4 v;
            v = *(const float4*)(Ab + 0 * RANK + 4 * j);
            a0[4*j]=v.x; a0[4*j+1]=v.y; a0[4*j+2]=v.z; a0[4*j+3]=v.w;
            v = *(const float4*)(Ab + 1 * RANK + 4 * j);
            a1[4*j]=v.x; a1[4*j+1]=v.y; a1[4*j+2]=v.z; a1[4*j+3]=v.w;
            v = *(const float4*)(Ab + 2 * RANK + 4 * j);
            a2[4*j]=v.x; a2[4*j+1]=v.y; a2[4*j+2]=v.z; a2[4*j+3]=v.w;
            v = *(const float4*)(Ab + 3 * RANK + 4 * j);
            a3[4*j]=v.x; a3[4*j+1]=v.y; a3[4*j+2]=v.z; a3[4*j+3]=v.w;
        }
#pragma unroll
        for (int r = 0; r < 16; ++r) {
            ap01[r] = pack2(a0[r], a1[r]);
            ap23[r] = pack2(a2[r], a3[r]);
        }
    }

    // fused reduce (8 split partials) + duplicate staging: 2 threads per row
    {
        const int row  = tid >> 1;
        const int half = tid & 1;
        const float* base = g_bx + ((size_t)b * SEQ + n0 + row) * RANK + half * 8;
        float4 u = make_float4(0.f, 0.f, 0.f, 0.f);
        float4 v = make_float4(0.f, 0.f, 0.f, 0.f);
#pragma unroll
        for (int s = 0; s < P1_SPLIT; ++s) {
            const float4* p =
                (const float4*)(base + (size_t)s * BATCH * SEQ * RANK);
            const float4 pa = p[0], pb = p[1];
            u.x += pa.x; u.y += pa.y; u.z += pa.z; u.w += pa.w;
            v.x += pb.x; v.y += pb.y; v.z += pb.z; v.w += pb.w;
        }
        const float w[8] = {u.x, u.y, u.z, u.w, v.x, v.y, v.z, v.w};
#pragma unroll
        for (int i = 0; i < 4; ++i) {
            ulonglong2 e;
            e.x = pack2(w[2*i],   w[2*i]);
            e.y = pack2(w[2*i+1], w[2*i+1]);
            bxd[row * BXP + half * 4 + i] = e;
        }
    }
    __syncthreads();

    float4* outp = (float4*)(out + ((size_t)b * SEQ + n0) * OUTF + o);

#pragma unroll 1
    for (int n = 0; n < ROWS2; n += 2) {
        const ulonglong2* r0 = bxd + n * BXP;
        const ulonglong2* r1 = r0 + BXP;
        ull A0=0, A1=0, A2=0, A3=0, B0=0, B1=0, B2=0, B3=0;
#pragma unroll
        for (int p = 0; p < 4; ++p) {            // ranks 0-7
            const ulonglong2 ba = r0[p], bb = r1[p];
            fma2(A0, ap01[2*p], ba.x); fma2(A0, ap01[2*p+1], ba.y);
            fma2(A1, ap23[2*p], ba.x); fma2(A1, ap23[2*p+1], ba.y);
            fma2(B0, ap01[2*p], bb.x); fma2(B0, ap01[2*p+1], bb.y);
            fma2(B1, ap23[2*p], bb.x); fma2(B1, ap23[2*p+1], bb.y);
        }
#pragma unroll
        for (int p = 4; p < 8; ++p) {            // ranks 8-15
            const ulonglong2 ba = r0[p], bb = r1[p];
            fma2(A2, ap01[2*p], ba.x); fma2(A2, ap01[2*p+1], ba.y);
            fma2(A3, ap23[2*p], ba.x); fma2(A3, ap23[2*p+1], ba.y);
            fma2(B2, ap01[2*p], bb.x); fma2(B2, ap01[2*p+1], bb.y);
            fma2(B3, ap23[2*p], bb.x); fma2(B3, ap23[2*p+1], bb.y);
        }
        float4 res0, res1;
        float l0, h0, l1, h1;
        unpack2(l0, h0, A0); unpack2(l1, h1, A2); res0.x = l0+l1; res0.y = h0+h1;
        unpack2(l0, h0, A1); unpack2(l1, h1, A3); res0.z = l0+l1; res0.w = h0+h1;
        unpack2(l0, h0, B0); unpack2(l1, h1, B2); res1.x = l0+l1; res1.y = h0+h1;
        unpack2(l0, h0, B1); unpack2(l1, h1, B3); res1.z = l0+l1; res1.w = h0+h1;
        outp[(size_t)n       * (OUTF / 4)] = res0;
        outp[(size_t)(n + 1) * (OUTF / 4)] = res1;
    }
}

// ---------------------------------------------------------------------------
extern "C" void kernel_launch(void* const* d_in, const int* in_sizes, int n_in,
                              void* d_out, int out_size)
{
    const float* x   = (const float*)d_in[0];   // [4,2048,4096]
    const float* Aw  = (const float*)d_in[1];   // [8,4096,16]
    const float* Bw  = (const float*)d_in[2];   // [8,16,4096]
    const int*   ids = (const int*)  d_in[3];   // [4]
    float*       out = (float*)d_out;           // [4,2048,4096]

    lora_conv_b<<<(8 * KS_TOT * 32) / 256, 256>>>(Bw);   // 256 CTAs, ~3us

    dim3 g1(SEQ / P1_ROWS, BATCH, P1_SPLIT);             // (16,4,8) = 512 CTAs
    lora_p1_mma<<<g1, P1_T>>>(x, ids);

    dim3 g2(OUTF / OTILE, SEQ / ROWS2, BATCH);           // (4,16,4) = 256 CTAs
    lora_phase2<<<g2, T2>>>(Aw, ids, out);
}

// round 12
// speedup vs baseline: 1.3845x; 1.2036x over previous
#include <cuda_runtime.h>
#include <cstdint>

#define BATCH 4
#define SEQ   2048
#define INF   4096
#define OUTF  4096
#define RANK  16
// SCALING = 16/16 = 1.0f (elided)

// ---- phase-1 (warp MMA) ----
#define P1_T      128                 // 4 warps
#define P1_ROWS   64                  // rows per CTA (4 warps x m16)
#define P1_SPLIT  8
#define KS_TOT    (INF / 16)          // 256 k-steps
#define KS_SPLIT  (KS_TOT / P1_SPLIT) // 32

// ---- phase-2 (SIMT, proven R7) ----
#define T2     256
#define ROWS2  128
#define OPT    4
#define OTILE  (T2 * OPT)             // 1024
#define BXP    9

typedef unsigned long long ull;

// scratch
__device__ float    g_bx[P1_SPLIT * BATCH * SEQ * RANK];   // 4 MB fp32 partials
__device__ uint32_t g_Bc[8 * 2 * KS_TOT * 2 * 2 * 32];     // 2 MB packed B

// ---- helpers --------------------------------------------------------------
__device__ __forceinline__ void fma2(ull& d, ull a, ull b) {
    asm("fma.rn.f32x2 %0, %1, %2, %0;" : "+l"(d) : "l"(a), "l"(b));
}
__device__ __forceinline__ ull pack2(float lo, float hi) {
    ull d; asm("mov.b64 %0, {%1, %2};" : "=l"(d) : "f"(lo), "f"(hi)); return d;
}
__device__ __forceinline__ void unpack2(float& lo, float& hi, ull d) {
    asm("mov.b64 {%0, %1}, %2;" : "=f"(lo), "=f"(hi) : "l"(d));
}
__device__ __forceinline__ uint32_t bfhi2(float f0, float f1) {
    return __byte_perm(__float_as_uint(f0), __float_as_uint(f1), 0x7632);
}
__device__ __forceinline__ uint32_t bflo2(float f0, float f1) {
    const float l0 = f0 - __uint_as_float(__float_as_uint(f0) & 0xFFFF0000u);
    const float l1 = f1 - __uint_as_float(__float_as_uint(f1) & 0xFFFF0000u);
    return __byte_perm(__float_as_uint(l0), __float_as_uint(l1), 0x7632);
}
__device__ __forceinline__ void mma16816(float* d,
    uint32_t a0, uint32_t a1, uint32_t a2, uint32_t a3,
    uint32_t b0, uint32_t b1)
{
    asm volatile(
        "mma.sync.aligned.m16n8k16.row.col.f32.bf16.bf16.f32 "
        "{%0,%1,%2,%3}, {%4,%5,%6,%7}, {%8,%9}, {%0,%1,%2,%3};"
        : "+f"(d[0]), "+f"(d[1]), "+f"(d[2]), "+f"(d[3])
        : "r"(a0), "r"(a1), "r"(a2), "r"(a3), "r"(b0), "r"(b1));
}

// ---------------------------------------------------------------------------
// K0: pack B[8][16][4096] -> b-frag bf16 hi/lo.
// word idx = ((((a*2+h)*KS_TOT + ks)*2 + j)*2 + t)*32 + lane
//   element: rank = t*8 + lane>>2, k = ks*16 + j*8 + (lane&3)*2 (+pair)
// ---------------------------------------------------------------------------
__global__ void lora_conv_b(const float* __restrict__ Bw)
{
    const int idx  = blockIdx.x * blockDim.x + threadIdx.x;   // 8*256*32
    const int lane = idx & 31;
    const int ks   = (idx >> 5) & (KS_TOT - 1);
    const int a    = idx >> 13;
#pragma unroll
    for (int t = 0; t < 2; ++t) {
        const int r = t * 8 + (lane >> 2);
        const float* p = Bw + ((size_t)a * RANK + r) * INF + ks * 16 + (lane & 3) * 2;
#pragma unroll
        for (int j = 0; j < 2; ++j) {
            const float f0 = p[j * 8], f1 = p[j * 8 + 1];
            const uint32_t off = (uint32_t)(((ks * 2 + j) * 2 + t) * 32 + lane);
            g_Bc[(uint32_t)(a * 2 + 0) * (KS_TOT * 128) + off] = bfhi2(f0, f1);
            g_Bc[(uint32_t)(a * 2 + 1) * (KS_TOT * 128) + off] = bflo2(f0, f1);
        }
    }
}

// ---------------------------------------------------------------------------
// K1: phase-1 tensor MMA (split-bf16, 3 terms, 6 independent acc chains).
// 128-thread CTAs (4 warps x m16 rows), K split 8 -> 1024 CTAs (~7/SM).
// ---------------------------------------------------------------------------
__global__ __launch_bounds__(P1_T, 6) void lora_p1_mma(
    const float* __restrict__ x,
    const int*   __restrict__ ids)
{
    const int tid  = threadIdx.x;
    const int wid  = tid >> 5;
    const int lane = tid & 31;
    const int tig  = lane & 3;
    const int b    = blockIdx.y;
    const int sp   = blockIdx.z;
    const int aid  = ids[b];

    const int row0 = blockIdx.x * P1_ROWS + wid * 16 + (lane >> 2);
    const float* xr0 = x + ((size_t)b * SEQ + row0) * INF;
    const float* xr8 = xr0 + 8 * INF;

    const uint32_t* Bhi = g_Bc + (size_t)(aid * 2 + 0) * (KS_TOT * 128);
    const uint32_t* Blo = g_Bc + (size_t)(aid * 2 + 1) * (KS_TOT * 128);

    // 6 independent chains: {ranks 0-7, 8-15} x {hi*hi, lo*hi, hi*lo}
    float c0h[4] = {0,0,0,0}, c0m[4] = {0,0,0,0}, c0l[4] = {0,0,0,0};
    float c1h[4] = {0,0,0,0}, c1m[4] = {0,0,0,0}, c1l[4] = {0,0,0,0};

    const int ks0 = sp * KS_SPLIT;
#pragma unroll 4
    for (int ks = ks0; ks < ks0 + KS_SPLIT; ++ks) {
        const int k = ks * 16 + tig * 2;
        const float2 f0 = *(const float2*)(xr0 + k);
        const float2 f1 = *(const float2*)(xr8 + k);
        const float2 f2 = *(const float2*)(xr0 + k + 8);
        const float2 f3 = *(const float2*)(xr8 + k + 8);

        const uint32_t ah0 = bfhi2(f0.x, f0.y), ah1 = bfhi2(f1.x, f1.y);
        const uint32_t ah2 = bfhi2(f2.x, f2.y), ah3 = bfhi2(f3.x, f3.y);
        const uint32_t al0 = bflo2(f0.x, f0.y), al1 = bflo2(f1.x, f1.y);
        const uint32_t al2 = bflo2(f2.x, f2.y), al3 = bflo2(f3.x, f3.y);

        const uint32_t* bp = Bhi + ks * 128 + lane;
        const uint32_t* lp = Blo + ks * 128 + lane;
        const uint32_t bh00 = bp[0],  bh01 = bp[64];   // ranks 0-7
        const uint32_t bh10 = bp[32], bh11 = bp[96];   // ranks 8-15
        const uint32_t bl00 = lp[0],  bl01 = lp[64];
        const uint32_t bl10 = lp[32], bl11 = lp[96];

        mma16816(c0h, ah0, ah1, ah2, ah3, bh00, bh01);   // hi*hi
        mma16816(c1h, ah0, ah1, ah2, ah3, bh10, bh11);
        mma16816(c0m, al0, al1, al2, al3, bh00, bh01);   // lo*hi
        mma16816(c1m, al0, al1, al2, al3, bh10, bh11);
        mma16816(c0l, ah0, ah1, ah2, ah3, bl00, bl01);   // hi*lo
        mma16816(c1l, ah0, ah1, ah2, ah3, bl10, bl11);
    }

    float acc0[4], acc1[4];
#pragma unroll
    for (int i = 0; i < 4; ++i) {
        acc0[i] = c0h[i] + c0m[i] + c0l[i];
        acc1[i] = c1h[i] + c1m[i] + c1l[i];
    }

    float* d0 = g_bx + ((size_t)(sp * BATCH + b) * SEQ + row0) * RANK;
    float* d8 = d0 + 8 * RANK;
    *(float2*)(d0 + tig * 2)     = make_float2(acc0[0], acc0[1]);
    *(float2*)(d8 + tig * 2)     = make_float2(acc0[2], acc0[3]);
    *(float2*)(d0 + 8 + tig * 2) = make_float2(acc1[0], acc1[1]);
    *(float2*)(d8 + 8 + tig * 2) = make_float2(acc1[2], acc1[3]);
}

// ---------------------------------------------------------------------------
// Phase 2 (fused split-reduce): out[b][n][o] = sum_r Bx[b][n][r]*A[aid][o][r]
// Thread owns 4 consecutive o; A pairs (32 ull) in regs; Bx dup'd in smem.
// 2 rows/iter -> 8 independent fma2 chains. 2 CTAs/SM.  [R7, measured ~34us]
// ---------------------------------------------------------------------------
__global__ __launch_bounds__(T2, 2) void lora_phase2(
    const float* __restrict__ Aw,
    const int*   __restrict__ ids,
    float*       __restrict__ out)
{
    __shared__ ulonglong2 bxd[ROWS2 * BXP];      // 18.4 KB

    const int tid = threadIdx.x;
    const int o   = blockIdx.x * OTILE + tid * OPT;
    const int n0  = blockIdx.y * ROWS2;
    const int b   = blockIdx.z;
    const int aid = ids[b];

    // A pairs: ap01[r] = (A[o][r], A[o+1][r]); ap23[r] = (A[o+2][r], A[o+3][r])
    ull ap01[16], ap23[16];
    {
        const float* Ab = Aw + ((size_t)aid * OUTF + o) * RANK;
        float a0[16], a1[16], a2[16], a3[16];
#pragma unroll
        for (int j = 0; j < 4; ++j) {
            float4 v;
            v = *(const float4*)(Ab + 0 * RANK + 4 * j);
            a0[4*j]=v.x; a0[4*j+1]=v.y; a0[4*j+2]=v.z; a0[4*j+3]=v.w;
            v = *(const float4*)(Ab + 1 * RANK + 4 * j);
            a1[4*j]=v.x; a1[4*j+1]=v.y; a1[4*j+2]=v.z; a1[4*j+3]=v.w;
            v = *(const float4*)(Ab + 2 * RANK + 4 * j);
            a2[4*j]=v.x; a2[4*j+1]=v.y; a2[4*j+2]=v.z; a2[4*j+3]=v.w;
            v = *(const float4*)(Ab + 3 * RANK + 4 * j);
            a3[4*j]=v.x; a3[4*j+1]=v.y; a3[4*j+2]=v.z; a3[4*j+3]=v.w;
        }
#pragma unroll
        for (int r = 0; r < 16; ++r) {
            ap01[r] = pack2(a0[r], a1[r]);
            ap23[r] = pack2(a2[r], a3[r]);
        }
    }

    // fused reduce (8 split partials) + duplicate staging: 2 threads per row
    {
        const int row  = tid >> 1;
        const int half = tid & 1;
        const float* base = g_bx + ((size_t)b * SEQ + n0 + row) * RANK + half * 8;
        float4 u = make_float4(0.f, 0.f, 0.f, 0.f);
        float4 v = make_float4(0.f, 0.f, 0.f, 0.f);
#pragma unroll
        for (int s = 0; s < P1_SPLIT; ++s) {
            const float4* p =
                (const float4*)(base + (size_t)s * BATCH * SEQ * RANK);
            const float4 pa = p[0], pb = p[1];
            u.x += pa.x; u.y += pa.y; u.z += pa.z; u.w += pa.w;
            v.x += pb.x; v.y += pb.y; v.z += pb.z; v.w += pb.w;
        }
        const float w[8] = {u.x, u.y, u.z, u.w, v.x, v.y, v.z, v.w};
#pragma unroll
        for (int i = 0; i < 4; ++i) {
            ulonglong2 e;
            e.x = pack2(w[2*i],   w[2*i]);
            e.y = pack2(w[2*i+1], w[2*i+1]);
            bxd[row * BXP + half * 4 + i] = e;
        }
    }
    __syncthreads();

    float4* outp = (float4*)(out + ((size_t)b * SEQ + n0) * OUTF + o);

#pragma unroll 1
    for (int n = 0; n < ROWS2; n += 2) {
        const ulonglong2* r0 = bxd + n * BXP;
        const ulonglong2* r1 = r0 + BXP;
        ull A0=0, A1=0, A2=0, A3=0, B0=0, B1=0, B2=0, B3=0;
#pragma unroll
        for (int p = 0; p < 4; ++p) {            // ranks 0-7
            const ulonglong2 ba = r0[p], bb = r1[p];
            fma2(A0, ap01[2*p], ba.x); fma2(A0, ap01[2*p+1], ba.y);
            fma2(A1, ap23[2*p], ba.x); fma2(A1, ap23[2*p+1], ba.y);
            fma2(B0, ap01[2*p], bb.x); fma2(B0, ap01[2*p+1], bb.y);
            fma2(B1, ap23[2*p], bb.x); fma2(B1, ap23[2*p+1], bb.y);
        }
#pragma unroll
        for (int p = 4; p < 8; ++p) {            // ranks 8-15
            const ulonglong2 ba = r0[p], bb = r1[p];
            fma2(A2, ap01[2*p], ba.x); fma2(A2, ap01[2*p+1], ba.y);
            fma2(A3, ap23[2*p], ba.x); fma2(A3, ap23[2*p+1], ba.y);
            fma2(B2, ap01[2*p], bb.x); fma2(B2, ap01[2*p+1], bb.y);
            fma2(B3, ap23[2*p], bb.x); fma2(B3, ap23[2*p+1], bb.y);
        }
        float4 res0, res1;
        float l0, h0, l1, h1;
        unpack2(l0, h0, A0); unpack2(l1, h1, A2); res0.x = l0+l1; res0.y = h0+h1;
        unpack2(l0, h0, A1); unpack2(l1, h1, A3); res0.z = l0+l1; res0.w = h0+h1;
        unpack2(l0, h0, B0); unpack2(l1, h1, B2); res1.x = l0+l1; res1.y = h0+h1;
        unpack2(l0, h0, B1); unpack2(l1, h1, B3); res1.z = l0+l1; res1.w = h0+h1;
        outp[(size_t)n       * (OUTF / 4)] = res0;
        outp[(size_t)(n + 1) * (OUTF / 4)] = res1;
    }
}

// ---------------------------------------------------------------------------
extern "C" void kernel_launch(void* const* d_in, const int* in_sizes, int n_in,
                              void* d_out, int out_size)
{
    const float* x   = (const float*)d_in[0];   // [4,2048,4096]
    const float* Aw  = (const float*)d_in[1];   // [8,4096,16]
    const float* Bw  = (const float*)d_in[2];   // [8,16,4096]
    const int*   ids = (const int*)  d_in[3];   // [4]
    float*       out = (float*)d_out;           // [4,2048,4096]

    lora_conv_b<<<(8 * KS_TOT * 32) / 256, 256>>>(Bw);   // 256 CTAs

    dim3 g1(SEQ / P1_ROWS, BATCH, P1_SPLIT);             // (32,4,8) = 1024 CTAs
    lora_p1_mma<<<g1, P1_T>>>(x, ids);

    dim3 g2(OUTF / OTILE, SEQ / ROWS2, BATCH);           // (4,16,4) = 256 CTAs
    lora_phase2<<<g2, T2>>>(Aw, ids, out);
}